// round 13
// baseline (speedup 1.0000x reference)
#include <cuda_runtime.h>

// Net_24395414241687 — two-layer NNConv GNN + readout ending in
// log_softmax over axis=1 of a [G, 1] = [1024, 1] tensor.
//
// log_softmax over a length-1 axis is identically zero:
//   log_softmax(x) = x - logsumexp(x) = x - x = 0  (bit-exact in JAX's
//   max-subtracted formulation; all upstream values are finite).
// The reference output is therefore exactly zeros([1024, 1]) for every
// input — the entire GNN pipeline (2x NNConv edge-MLP GEMMs, scatter-means,
// readout MLP, ~1.6 GFLOP) is dead code, eliminated by proof. The only
// mandatory work is un-poisoning d_out (harness fills it with 0xAA).
//
// Node-type search (all graph-capturable write mechanisms measured):
//   R1 grid=4 kernel node:       4.86us e2e
//   R3 1-CTA kernel node:        4.61us e2e  (kernel-node front-end ~3.3us,
//                                grid-invariant)
//   R5 D2D memcpy node:          4.61us e2e
//   memset node (9 benches):     3.36 / 3.39 / 3.42 / 3.90 / 3.94 /
//                                3.97 x3 / 4.00us — identical binary on
//                                every run; the spread is hold-to-hold
//                                clock/environment variance (fast holds
//                                ~3.4us, typical ~3.95us). rel_err = 0
//                                exact on all runs (output constant-zero
//                                by construction, seed-independent).
// Remaining e2e is the harness's single-node graph-replay dispatch plus
// the memset engine front-end — not reducible from inside kernel_launch.
// FINAL: cudaMemsetAsync node.

extern "C" void kernel_launch(void* const* d_in, const int* in_sizes, int n_in,
                              void* d_out, int out_size) {
    (void)d_in; (void)in_sizes; (void)n_in;
    cudaMemsetAsync(d_out, 0, (size_t)out_size * sizeof(float), 0);
}

// round 14
// speedup vs baseline: 1.1495x; 1.1495x over previous
#include <cuda_runtime.h>

// Net_24395414241687 — two-layer NNConv GNN + readout ending in
// log_softmax over axis=1 of a [G, 1] = [1024, 1] tensor.
//
// log_softmax over a length-1 axis is identically zero:
//   log_softmax(x) = x - logsumexp(x) = x - x = 0  (bit-exact in JAX's
//   max-subtracted formulation; all upstream values are finite).
// The reference output is therefore exactly zeros([1024, 1]) for every
// input — the entire GNN pipeline (2x NNConv edge-MLP GEMMs, scatter-means,
// readout MLP, ~1.6 GFLOP) is dead code, eliminated by proof. The only
// mandatory work is un-poisoning d_out (harness fills it with 0xAA).
//
// Node-type search (all graph-capturable write mechanisms measured):
//   R1 grid=4 kernel node:       4.86us e2e
//   R3 1-CTA kernel node:        4.61us e2e  (kernel-node front-end ~3.3us,
//                                grid-invariant)
//   R5 D2D memcpy node:          4.61us e2e
//   memset node (10 benches):    3.36 / 3.39 / 3.42 / 3.90 / 3.94 x2 /
//                                3.97 x3 / 4.00us — identical binary on
//                                every run; the spread is hold-to-hold
//                                clock/environment variance (fast holds
//                                ~3.4us, typical ~3.95us). rel_err = 0
//                                exact on all runs (output constant-zero
//                                by construction, seed-independent).
// Remaining e2e is the harness's single-node graph-replay dispatch plus
// the memset engine front-end — not reducible from inside kernel_launch.
// FINAL: cudaMemsetAsync node.

extern "C" void kernel_launch(void* const* d_in, const int* in_sizes, int n_in,
                              void* d_out, int out_size) {
    (void)d_in; (void)in_sizes; (void)n_in;
    cudaMemsetAsync(d_out, 0, (size_t)out_size * sizeof(float), 0);
}